// round 1
// baseline (speedup 1.0000x reference)
#include <cuda_runtime.h>

// SSM S4 diagonal scan: L=8192 timesteps, C=512 channels, N=64 states.
// y[t,c] = sum_n C[n] * h[t,c,n],  h[t] = Abar*h[t-1] + Bbar*x[t]
// Rescaled state u = h/Bbar:  u[t] = Abar*u[t-1] + x[t],  y = sum_n (C[n]*Bbar[n]) * u
// Chunked parallel scan over time: P chunks of B steps.
//   K1: per-chunk local final states (zero init)
//   K2: carry scan across chunks with factor Abar^B
//   K3: in-chunk scan seeded with carry-in, emits y

#define LT   8192
#define CH   512
#define NS   64
#define BCH  128          // chunk length
#define NP   (LT / BCH)   // 64 chunks
#define CPB  64           // channels per block

__device__ float g_a[NS];    // Abar
__device__ float g_w[NS];    // C * Bbar
__device__ float g_aB[NS];   // Abar^BCH
__device__ float g_Hl[(size_t)NP * CH * NS];   // local chunk-final states (u-domain)
__device__ float g_Hin[(size_t)NP * CH * NS];  // carry-in state per chunk (u-domain)

__global__ void k_init(const float* __restrict__ logA,
                       const float* __restrict__ Bp,
                       const float* __restrict__ Cp) {
    int n = threadIdx.x;
    if (n < NS) {
        const float dt = 1.0f / 4096.0f;
        float A    = -expf(logA[n]);           // mirror reference fp32 ops
        float Abar = expf(A * dt);
        float Bbar = (Abar - 1.0f) * Bp[n] / A;
        g_a[n] = Abar;
        g_w[n] = Cp[n] * Bbar;
        double p = 1.0, ad = (double)Abar;
        #pragma unroll 1
        for (int i = 0; i < BCH; i++) p *= ad;
        g_aB[n] = (float)p;
    }
}

// K1: local scan with zero init; store only the final state of each chunk.
__global__ __launch_bounds__(256) void k_local(const float* __restrict__ x) {
    __shared__ float xs[BCH][CPB];
    const int p  = blockIdx.x;
    const int c0 = blockIdx.y * CPB;
    const int tid = threadIdx.x;

    for (int idx = tid; idx < BCH * CPB; idx += 256) {
        int j = idx >> 6, cl = idx & 63;
        xs[j][cl] = x[(size_t)(p * BCH + j) * CH + c0 + cl];
    }
    __syncthreads();

    const int g  = tid & 3;       // state group (16 states each)
    const int cl = tid >> 2;      // channel within block
    const int n0 = g * 16;

    float a[16], u[16];
    #pragma unroll
    for (int k = 0; k < 16; k++) { a[k] = g_a[n0 + k]; u[k] = 0.0f; }

    #pragma unroll 4
    for (int j = 0; j < BCH; j++) {
        float xv = xs[j][cl];
        #pragma unroll
        for (int k = 0; k < 16; k++) u[k] = fmaf(a[k], u[k], xv);
    }

    float* dst = &g_Hl[((size_t)p * CH + (c0 + cl)) * NS + n0];
    #pragma unroll
    for (int k = 0; k < 16; k += 4)
        *(float4*)(dst + k) = make_float4(u[k], u[k + 1], u[k + 2], u[k + 3]);
}

// K2: serial carry scan over chunks, one thread per (channel, state).
__global__ __launch_bounds__(256) void k_scan() {
    int idx = blockIdx.x * blockDim.x + threadIdx.x;  // idx = c*NS + n
    if (idx >= CH * NS) return;
    int n = idx & (NS - 1);
    float aB = g_aB[n];
    float S = 0.0f;
    #pragma unroll 4
    for (int p = 0; p < NP; p++) {
        g_Hin[(size_t)p * CH * NS + idx] = S;
        S = fmaf(aB, S, g_Hl[(size_t)p * CH * NS + idx]);
    }
}

// K3: full in-chunk scan seeded with carry-in; emit y.
__global__ __launch_bounds__(256) void k_final(const float* __restrict__ x,
                                               float* __restrict__ y) {
    __shared__ float xs[BCH][CPB];
    __shared__ float ys[BCH][CPB];
    const int p  = blockIdx.x;
    const int c0 = blockIdx.y * CPB;
    const int tid = threadIdx.x;

    for (int idx = tid; idx < BCH * CPB; idx += 256) {
        int j = idx >> 6, cl = idx & 63;
        xs[j][cl] = x[(size_t)(p * BCH + j) * CH + c0 + cl];
    }
    __syncthreads();

    const int g  = tid & 3;
    const int cl = tid >> 2;
    const int n0 = g * 16;

    float a[16], w[16], u[16];
    const float* hin = &g_Hin[((size_t)p * CH + (c0 + cl)) * NS + n0];
    #pragma unroll
    for (int k = 0; k < 16; k++) {
        a[k] = g_a[n0 + k];
        w[k] = g_w[n0 + k];
        u[k] = hin[k];
    }

    #pragma unroll 2
    for (int j = 0; j < BCH; j++) {
        float xv = xs[j][cl];
        float s0 = 0.f, s1 = 0.f, s2 = 0.f, s3 = 0.f;
        #pragma unroll
        for (int k = 0; k < 16; k += 4) {
            u[k]     = fmaf(a[k],     u[k],     xv); s0 = fmaf(w[k],     u[k],     s0);
            u[k + 1] = fmaf(a[k + 1], u[k + 1], xv); s1 = fmaf(w[k + 1], u[k + 1], s1);
            u[k + 2] = fmaf(a[k + 2], u[k + 2], xv); s2 = fmaf(w[k + 2], u[k + 2], s2);
            u[k + 3] = fmaf(a[k + 3], u[k + 3], xv); s3 = fmaf(w[k + 3], u[k + 3], s3);
        }
        float v = (s0 + s1) + (s2 + s3);
        v += __shfl_xor_sync(0xffffffffu, v, 1);
        v += __shfl_xor_sync(0xffffffffu, v, 2);
        if (g == 0) ys[j][cl] = v;
    }
    __syncthreads();

    for (int idx = tid; idx < BCH * CPB; idx += 256) {
        int j = idx >> 6, cl = idx & 63;
        y[(size_t)(p * BCH + j) * CH + c0 + cl] = ys[j][cl];
    }
}

extern "C" void kernel_launch(void* const* d_in, const int* in_sizes, int n_in,
                              void* d_out, int out_size) {
    const float* x    = (const float*)d_in[0];
    const float* logA = (const float*)d_in[1];
    const float* Bp   = (const float*)d_in[2];
    const float* Cp   = (const float*)d_in[3];
    float* y = (float*)d_out;

    k_init<<<1, 64>>>(logA, Bp, Cp);
    dim3 grid(NP, CH / CPB);
    k_local<<<grid, 256>>>(x);
    k_scan<<<(CH * NS + 255) / 256, 256>>>();
    k_final<<<grid, 256>>>(x, y);
}

// round 5
// speedup vs baseline: 1.0820x; 1.0820x over previous
#include <cuda_runtime.h>

// SSM S4 diagonal scan: L=8192, C=512, N=64.
// u[t] = Abar*u[t-1] + x[t] (rescaled state), y[t] = sum_n (C*Bbar)[n] * u[t,n]
// 3-pass chunked scan with packed f32x2 FMAs, transposed smem x tiles,
// 4x4 shfl sum-transpose reduction, and in-place y into the x tile.

#define LT   8192
#define CH   512
#define NS   64
#define BCH  128          // chunk length
#define NP   (LT / BCH)   // 64 chunks
#define CPB  64           // channels per block
#define XPAD 132          // padded row (floats): 528B rows, 16B-aligned, conflict-free

typedef unsigned long long ull;

__device__ __align__(16) float g_a[NS];    // Abar
__device__ __align__(16) float g_w[NS];    // C * Bbar
__device__ __align__(16) float g_aB[NS];   // Abar^BCH
__device__ __align__(16) float g_Hl[(size_t)NP * CH * NS];   // local chunk-final states
__device__ __align__(16) float g_Hin[(size_t)NP * CH * NS];  // carry-in per chunk

// ---- packed f32x2 helpers -------------------------------------------------
__device__ __forceinline__ ull f2fma(ull a, ull b, ull c) {
    ull d; asm("fma.rn.f32x2 %0,%1,%2,%3;" : "=l"(d) : "l"(a), "l"(b), "l"(c)); return d;
}
__device__ __forceinline__ ull f2mul(ull a, ull b) {
    ull d; asm("mul.rn.f32x2 %0,%1,%2;" : "=l"(d) : "l"(a), "l"(b)); return d;
}
__device__ __forceinline__ ull f2add(ull a, ull b) {
    ull d; asm("add.rn.f32x2 %0,%1,%2;" : "=l"(d) : "l"(a), "l"(b)); return d;
}
__device__ __forceinline__ ull f2bcast(float f) {
    ull r; asm("mov.b64 %0,{%1,%1};" : "=l"(r) : "f"(f)); return r;
}
__device__ __forceinline__ float f2hsum(ull v) {
    float lo, hi; asm("mov.b64 {%0,%1},%2;" : "=f"(lo), "=f"(hi) : "l"(v));
    return lo + hi;
}

// ---- init -----------------------------------------------------------------
__global__ void k_init(const float* __restrict__ logA,
                       const float* __restrict__ Bp,
                       const float* __restrict__ Cp) {
    int n = threadIdx.x;
    if (n < NS) {
        const float dt = 1.0f / 4096.0f;
        float A    = -expf(logA[n]);           // mirror reference fp32 ops
        float Abar = expf(A * dt);
        float Bbar = (Abar - 1.0f) * Bp[n] / A;
        g_a[n] = Abar;
        g_w[n] = Cp[n] * Bbar;
        double p = 1.0, ad = (double)Abar;
        #pragma unroll 1
        for (int i = 0; i < BCH; i++) p *= ad;
        g_aB[n] = (float)p;
    }
}

// ---- K1: local scan (zero init), store chunk-final states -----------------
__global__ __launch_bounds__(256) void k_local(const float* __restrict__ x) {
    __shared__ float xs[CPB][XPAD];
    const int p   = blockIdx.x;
    const int c0  = blockIdx.y * CPB;
    const int tid = threadIdx.x;

    // load x tile transposed: xs[cl][j]
    for (int i = tid; i < BCH * (CPB / 4); i += 256) {
        int j = i >> 4, q = i & 15;
        float4 v = *(const float4*)&x[(size_t)(p * BCH + j) * CH + c0 + q * 4];
        xs[q * 4 + 0][j] = v.x; xs[q * 4 + 1][j] = v.y;
        xs[q * 4 + 2][j] = v.z; xs[q * 4 + 3][j] = v.w;
    }
    __syncthreads();

    const int g  = tid & 3;       // state group (16 states = 8 f32x2 pairs)
    const int cl = tid >> 2;      // channel within block

    ull a2[8], u2[8];
    const ull* ga2 = (const ull*)g_a;
    #pragma unroll
    for (int k = 0; k < 8; k++) { a2[k] = ga2[g * 8 + k]; u2[k] = 0ull; }

    #pragma unroll 2
    for (int jb = 0; jb < BCH; jb += 4) {
        float4 xv = *(const float4*)&xs[cl][jb];
        float xq[4] = {xv.x, xv.y, xv.z, xv.w};
        #pragma unroll
        for (int s = 0; s < 4; s++) {
            ull xx = f2bcast(xq[s]);
            #pragma unroll
            for (int k = 0; k < 8; k++) u2[k] = f2fma(a2[k], u2[k], xx);
        }
    }

    ull* dst = (ull*)&g_Hl[((size_t)p * CH + (c0 + cl)) * NS + g * 16];
    #pragma unroll
    for (int k = 0; k < 8; k++) dst[k] = u2[k];
}

// ---- K2: carry scan across chunks (pairs of states) -----------------------
__global__ __launch_bounds__(256) void k_scan() {
    int idx = blockIdx.x * blockDim.x + threadIdx.x;   // pair index: c*32 + npair
    if (idx >= CH * NS / 2) return;
    int np = idx & 31;
    ull aB2 = ((const ull*)g_aB)[np];
    ull S = 0ull;
    const ull* Hl  = (const ull*)g_Hl;
    ull*       Hin = (ull*)g_Hin;
    const int stride = CH * NS / 2;
    #pragma unroll 4
    for (int p = 0; p < NP; p++) {
        Hin[(size_t)p * stride + idx] = S;
        S = f2fma(aB2, S, Hl[(size_t)p * stride + idx]);
    }
}

// ---- K3: seeded scan, emit y ----------------------------------------------
__global__ __launch_bounds__(256) void k_final(const float* __restrict__ x,
                                               float* __restrict__ y) {
    __shared__ float xs[CPB][XPAD];
    const int p   = blockIdx.x;
    const int c0  = blockIdx.y * CPB;
    const int tid = threadIdx.x;

    for (int i = tid; i < BCH * (CPB / 4); i += 256) {
        int j = i >> 4, q = i & 15;
        float4 v = *(const float4*)&x[(size_t)(p * BCH + j) * CH + c0 + q * 4];
        xs[q * 4 + 0][j] = v.x; xs[q * 4 + 1][j] = v.y;
        xs[q * 4 + 2][j] = v.z; xs[q * 4 + 3][j] = v.w;
    }
    __syncthreads();

    const int g  = tid & 3;
    const int cl = tid >> 2;

    ull a2[8], w2[8], u2[8];
    const ull* ga2 = (const ull*)g_a;
    const ull* gw2 = (const ull*)g_w;
    const ull* hin = (const ull*)&g_Hin[((size_t)p * CH + (c0 + cl)) * NS + g * 16];
    #pragma unroll
    for (int k = 0; k < 8; k++) {
        a2[k] = ga2[g * 8 + k];
        w2[k] = gw2[g * 8 + k];
        u2[k] = hin[k];
    }

    #pragma unroll 2
    for (int jb = 0; jb < BCH; jb += 4) {
        float4 xv = *(const float4*)&xs[cl][jb];
        float xq[4] = {xv.x, xv.y, xv.z, xv.w};
        float pt[4];
        #pragma unroll
        for (int s = 0; s < 4; s++) {
            ull xx = f2bcast(xq[s]);
            #pragma unroll
            for (int k = 0; k < 8; k++) u2[k] = f2fma(a2[k], u2[k], xx);
            ull s0 = f2mul(w2[0], u2[0]);
            ull s1 = f2mul(w2[1], u2[1]);
            #pragma unroll
            for (int k = 2; k < 8; k += 2) {
                s0 = f2fma(w2[k],     u2[k],     s0);
                s1 = f2fma(w2[k + 1], u2[k + 1], s1);
            }
            pt[s] = f2hsum(f2add(s0, s1));
        }
        // 4x4 sum-transpose across the quad: lane g ends with total for jb+g.
        float p0 = pt[0], p1 = pt[1], p2 = pt[2], p3 = pt[3];
        float send1 = (g & 1) ? p0 : p1;
        float r1 = __shfl_xor_sync(0xffffffffu, send1, 1);
        if (g & 1) p1 += r1; else p0 += r1;
        float send2 = (g & 1) ? p2 : p3;
        float r2 = __shfl_xor_sync(0xffffffffu, send2, 1);
        if (g & 1) p3 += r2; else p2 += r2;
        float send3 = (g & 2) ? ((g & 1) ? p1 : p0) : ((g & 1) ? p3 : p2);
        float r3 = __shfl_xor_sync(0xffffffffu, send3, 2);
        float total = ((g & 1) ? ((g & 2) ? p3 : p1) : ((g & 2) ? p2 : p0)) + r3;
        // in-place: y for timestep jb+g overwrites consumed x slot
        xs[cl][jb + g] = total;
    }
    __syncthreads();

    for (int i = tid; i < BCH * (CPB / 4); i += 256) {
        int j = i >> 4, q = i & 15;
        float4 v = make_float4(xs[q * 4 + 0][j], xs[q * 4 + 1][j],
                               xs[q * 4 + 2][j], xs[q * 4 + 3][j]);
        *(float4*)&y[(size_t)(p * BCH + j) * CH + c0 + q * 4] = v;
    }
}

extern "C" void kernel_launch(void* const* d_in, const int* in_sizes, int n_in,
                              void* d_out, int out_size) {
    const float* x    = (const float*)d_in[0];
    const float* logA = (const float*)d_in[1];
    const float* Bp   = (const float*)d_in[2];
    const float* Cp   = (const float*)d_in[3];
    float* y = (float*)d_out;

    k_init<<<1, 64>>>(logA, Bp, Cp);
    dim3 grid(NP, CH / CPB);
    k_local<<<grid, 256>>>(x);
    k_scan<<<(CH * NS / 2 + 255) / 256, 256>>>();
    k_final<<<grid, 256>>>(x, y);
}

// round 6
// speedup vs baseline: 1.1052x; 1.0214x over previous
#include <cuda_runtime.h>

// SSM S4 diagonal scan: L=8192, C=512, N=64.
// u[t] = Abar*u[t-1] + x[t] (rescaled), y[t] = sum_n (C*Bbar)[n] * u[t,n]
// 3-pass chunked scan; f32x2 FMAs; transposed smem x tiles; software-pipelined
// 4x4 shfl sum-transpose (3-stage, all shfl/LDS latency hidden); in-place y.

#define LT   8192
#define CH   512
#define NS   64
#define BCH  128          // chunk length
#define NP   (LT / BCH)   // 64 chunks
#define CPB  64           // channels per block
#define XPAD 132          // row stride (floats): 132 % 32 == 4 -> conflict-free

typedef unsigned long long ull;

__device__ __align__(16) float g_a[NS];    // Abar
__device__ __align__(16) float g_w[NS];    // C * Bbar
__device__ __align__(16) float g_aB[NS];   // Abar^BCH
__device__ __align__(16) float g_Hl[(size_t)NP * CH * NS];   // chunk-local final states
__device__ __align__(16) float g_Hin[(size_t)NP * CH * NS];  // carry-in per chunk

// ---- packed f32x2 helpers -------------------------------------------------
__device__ __forceinline__ ull f2fma(ull a, ull b, ull c) {
    ull d; asm("fma.rn.f32x2 %0,%1,%2,%3;" : "=l"(d) : "l"(a), "l"(b), "l"(c)); return d;
}
__device__ __forceinline__ ull f2mul(ull a, ull b) {
    ull d; asm("mul.rn.f32x2 %0,%1,%2;" : "=l"(d) : "l"(a), "l"(b)); return d;
}
__device__ __forceinline__ ull f2add(ull a, ull b) {
    ull d; asm("add.rn.f32x2 %0,%1,%2;" : "=l"(d) : "l"(a), "l"(b)); return d;
}
__device__ __forceinline__ ull f2bcast(float f) {
    ull r; asm("mov.b64 %0,{%1,%1};" : "=l"(r) : "f"(f)); return r;
}
__device__ __forceinline__ float f2hsum(ull v) {
    float lo, hi; asm("mov.b64 {%0,%1},%2;" : "=f"(lo), "=f"(hi) : "l"(v));
    return lo + hi;
}

// ---- init -----------------------------------------------------------------
__global__ void k_init(const float* __restrict__ logA,
                       const float* __restrict__ Bp,
                       const float* __restrict__ Cp) {
    int n = threadIdx.x;
    if (n < NS) {
        const float dt = 1.0f / 4096.0f;
        float A    = -expf(logA[n]);           // mirror reference fp32 ops
        float Abar = expf(A * dt);
        float Bbar = (Abar - 1.0f) * Bp[n] / A;
        g_a[n] = Abar;
        g_w[n] = Cp[n] * Bbar;
        double p = 1.0, ad = (double)Abar;
        #pragma unroll 1
        for (int i = 0; i < BCH; i++) p *= ad;
        g_aB[n] = (float)p;
    }
}

// ---- K1: local scan (zero init), store chunk-final states -----------------
__global__ __launch_bounds__(256, 3) void k_local(const float* __restrict__ x) {
    __shared__ float xs[CPB][XPAD];
    const int p   = blockIdx.x;
    const int c0  = blockIdx.y * CPB;
    const int tid = threadIdx.x;

    for (int i = tid; i < BCH * (CPB / 4); i += 256) {
        int j = i >> 4, q = i & 15;
        float4 v = *(const float4*)&x[(size_t)(p * BCH + j) * CH + c0 + q * 4];
        xs[q * 4 + 0][j] = v.x; xs[q * 4 + 1][j] = v.y;
        xs[q * 4 + 2][j] = v.z; xs[q * 4 + 3][j] = v.w;
    }
    __syncthreads();

    const int g  = tid & 3;       // state group (16 states = 8 f32x2 pairs)
    const int cl = tid >> 2;      // channel within block

    ull a2[8], u2[8];
    const ull* ga2 = (const ull*)g_a;
    #pragma unroll
    for (int k = 0; k < 8; k++) { a2[k] = ga2[g * 8 + k]; u2[k] = 0ull; }

    float4 xv = *(const float4*)&xs[cl][0];
    #pragma unroll 4
    for (int jb = 0; jb < BCH; jb += 4) {
        float4 cur = xv;
        int jn = (jb + 4 < BCH) ? jb + 4 : 0;
        xv = *(const float4*)&xs[cl][jn];        // prefetch next block
        float xq[4] = {cur.x, cur.y, cur.z, cur.w};
        #pragma unroll
        for (int s = 0; s < 4; s++) {
            ull xx = f2bcast(xq[s]);
            #pragma unroll
            for (int k = 0; k < 8; k++) u2[k] = f2fma(a2[k], u2[k], xx);
        }
    }

    ull* dst = (ull*)&g_Hl[((size_t)p * CH + (c0 + cl)) * NS + g * 16];
    #pragma unroll
    for (int k = 0; k < 8; k++) dst[k] = u2[k];
}

// ---- K2: carry scan across chunks (pairs of states) -----------------------
__global__ __launch_bounds__(128) void k_scan() {
    int idx = blockIdx.x * blockDim.x + threadIdx.x;   // pair index: c*32 + npair
    if (idx >= CH * NS / 2) return;
    int np = idx & 31;
    ull aB2 = ((const ull*)g_aB)[np];
    ull S = 0ull;
    const ull* Hl  = (const ull*)g_Hl;
    ull*       Hin = (ull*)g_Hin;
    const int stride = CH * NS / 2;
    #pragma unroll 8
    for (int p = 0; p < NP; p++) {
        Hin[(size_t)p * stride + idx] = S;
        S = f2fma(aB2, S, Hl[(size_t)p * stride + idx]);
    }
}

// ---- K3: seeded scan, emit y (3-stage pipelined reduction) ----------------
__global__ __launch_bounds__(256, 3) void k_final(const float* __restrict__ x,
                                                  float* __restrict__ y) {
    __shared__ float xs[CPB][XPAD];
    const int p   = blockIdx.x;
    const int c0  = blockIdx.y * CPB;
    const int tid = threadIdx.x;

    for (int i = tid; i < BCH * (CPB / 4); i += 256) {
        int j = i >> 4, q = i & 15;
        float4 v = *(const float4*)&x[(size_t)(p * BCH + j) * CH + c0 + q * 4];
        xs[q * 4 + 0][j] = v.x; xs[q * 4 + 1][j] = v.y;
        xs[q * 4 + 2][j] = v.z; xs[q * 4 + 3][j] = v.w;
    }
    __syncthreads();

    const int g  = tid & 3;
    const int cl = tid >> 2;

    ull a2[8], w2[8], u2[8];
    const ull* ga2 = (const ull*)g_a;
    const ull* gw2 = (const ull*)g_w;
    const ull* hin = (const ull*)&g_Hin[((size_t)p * CH + (c0 + cl)) * NS + g * 16];
    #pragma unroll
    for (int k = 0; k < 8; k++) {
        a2[k] = ga2[g * 8 + k];
        w2[k] = gw2[g * 8 + k];
        u2[k] = hin[k];
    }

    // stage 0: 4 steps of update+dot -> pt[0..3] (per-lane partials)
    auto compute4 = [&](const float4& xvc, float* pt) {
        float xq[4] = {xvc.x, xvc.y, xvc.z, xvc.w};
        #pragma unroll
        for (int s = 0; s < 4; s++) {
            ull xx = f2bcast(xq[s]);
            #pragma unroll
            for (int k = 0; k < 8; k++) u2[k] = f2fma(a2[k], u2[k], xx);
            ull s0 = f2mul(w2[0], u2[0]);
            ull s1 = f2mul(w2[1], u2[1]);
            #pragma unroll
            for (int k = 2; k < 8; k += 2) {
                s0 = f2fma(w2[k],     u2[k],     s0);
                s1 = f2fma(w2[k + 1], u2[k + 1], s1);
            }
            pt[s] = f2hsum(f2add(s0, s1));
        }
    };
    // stage 1a: issue level-1 butterflies (consumed one block later)
    auto level1 = [&](const float* pt, float& r1, float& r2) {
        float send1 = (g & 1) ? pt[0] : pt[1];
        r1 = __shfl_xor_sync(0xffffffffu, send1, 1);
        float send2 = (g & 1) ? pt[2] : pt[3];
        r2 = __shfl_xor_sync(0xffffffffu, send2, 1);
    };
    // stage 1b: combine level-1, issue level-2 (consumed one block later)
    auto level2 = [&](const float* pt, float r1, float r2, float& kept, float& r3) {
        float e01, e23;
        if (g & 1) { e01 = pt[1] + r1; e23 = pt[3] + r2; }
        else       { e01 = pt[0] + r1; e23 = pt[2] + r2; }
        float send3 = (g & 2) ? e01 : e23;
        kept        = (g & 2) ? e23 : e01;
        r3 = __shfl_xor_sync(0xffffffffu, send3, 2);
    };

    float ptA[4], ptB[4];
    float r1A, r2A, r1B, r2B, keptA, r3A, keptB, r3B;
    float4 xvA = *(const float4*)&xs[cl][0];
    float4 xvB = *(const float4*)&xs[cl][4];

    // prologue: blocks 0 (A) and 1 (B)
    {
        float4 c = xvA; xvA = *(const float4*)&xs[cl][8];
        compute4(c, ptA); level1(ptA, r1A, r2A);
    }
    {
        float4 c = xvB; xvB = *(const float4*)&xs[cl][12];
        compute4(c, ptB); level1(ptB, r1B, r2B);
        level2(ptA, r1A, r2A, keptA, r3A);
    }

    // steady: m = 2,4,...,30  (blocks m on A, m+1 on B)
    #pragma unroll 3
    for (int m = 2; m < BCH / 4; m += 2) {
        {
            int jn = 4 * m + 8;  if (jn > BCH - 4) jn = 0;
            float4 c = xvA; xvA = *(const float4*)&xs[cl][jn];
            compute4(c, ptA); level1(ptA, r1A, r2A);
            level2(ptB, r1B, r2B, keptB, r3B);
            xs[cl][4 * (m - 2) + g] = keptA + r3A;    // finalize block m-2
        }
        {
            int jn = 4 * m + 12; if (jn > BCH - 4) jn = 0;
            float4 c = xvB; xvB = *(const float4*)&xs[cl][jn];
            compute4(c, ptB); level1(ptB, r1B, r2B);
            level2(ptA, r1A, r2A, keptA, r3A);
            xs[cl][4 * (m - 1) + g] = keptB + r3B;    // finalize block m-1
        }
    }
    // epilogue: level2 for block 31 (B), finalize blocks 30 (A) and 31 (B)
    level2(ptB, r1B, r2B, keptB, r3B);
    xs[cl][BCH - 8 + g] = keptA + r3A;
    xs[cl][BCH - 4 + g] = keptB + r3B;

    __syncthreads();

    for (int i = tid; i < BCH * (CPB / 4); i += 256) {
        int j = i >> 4, q = i & 15;
        float4 v = make_float4(xs[q * 4 + 0][j], xs[q * 4 + 1][j],
                               xs[q * 4 + 2][j], xs[q * 4 + 3][j]);
        *(float4*)&y[(size_t)(p * BCH + j) * CH + c0 + q * 4] = v;
    }
}

extern "C" void kernel_launch(void* const* d_in, const int* in_sizes, int n_in,
                              void* d_out, int out_size) {
    const float* x    = (const float*)d_in[0];
    const float* logA = (const float*)d_in[1];
    const float* Bp   = (const float*)d_in[2];
    const float* Cp   = (const float*)d_in[3];
    float* y = (float*)d_out;

    k_init<<<1, 64>>>(logA, Bp, Cp);
    dim3 grid(NP, CH / CPB);
    k_local<<<grid, 256>>>(x);
    k_scan<<<(CH * NS / 2 + 127) / 128, 128>>>();
    k_final<<<grid, 256>>>(x, y);
}

// round 8
// speedup vs baseline: 1.2402x; 1.1222x over previous
#include <cuda_runtime.h>

// SSM S4 diagonal scan: L=8192, C=512, N=64.
// u[t] = Abar*u[t-1] + x[t] (rescaled), y[t] = sum_n (C*Bbar)[n] * u[t,n]
// 3-pass chunked scan; f32x2 FMAs; transposed smem x tiles; 4x4 shfl
// sum-transpose; in-place y. This round: 128-thread blocks, 1024 blocks,
// 7 blocks/SM -> single wave (tail eliminated); coefficients computed
// in-kernel (k_init launch removed).

#define LT   8192
#define CH   512
#define NS   64
#define BCH  128          // chunk length
#define NP   (LT / BCH)   // 64 chunks
#define CPB  32           // channels per block
#define XPAD 132          // row stride (floats): conflict-free for main-loop access
#define DT   (1.0f / 4096.0f)

typedef unsigned long long ull;

__device__ __align__(16) float g_Hl[(size_t)NP * CH * NS];   // chunk-local final states
__device__ __align__(16) float g_Hin[(size_t)NP * CH * NS];  // carry-in per chunk

// ---- packed f32x2 helpers -------------------------------------------------
__device__ __forceinline__ ull f2fma(ull a, ull b, ull c) {
    ull d; asm("fma.rn.f32x2 %0,%1,%2,%3;" : "=l"(d) : "l"(a), "l"(b), "l"(c)); return d;
}
__device__ __forceinline__ ull f2mul(ull a, ull b) {
    ull d; asm("mul.rn.f32x2 %0,%1,%2;" : "=l"(d) : "l"(a), "l"(b)); return d;
}
__device__ __forceinline__ ull f2add(ull a, ull b) {
    ull d; asm("add.rn.f32x2 %0,%1,%2;" : "=l"(d) : "l"(a), "l"(b)); return d;
}
__device__ __forceinline__ ull f2bcast(float f) {
    ull r; asm("mov.b64 %0,{%1,%1};" : "=l"(r) : "f"(f)); return r;
}
__device__ __forceinline__ ull f2pack(float lo, float hi) {
    ull r; asm("mov.b64 %0,{%1,%2};" : "=l"(r) : "f"(lo), "f"(hi)); return r;
}
__device__ __forceinline__ float f2hsum(ull v) {
    float lo, hi; asm("mov.b64 {%0,%1},%2;" : "=f"(lo), "=f"(hi) : "l"(v));
    return lo + hi;
}

// Abar for state n — identical fp32 op sequence in every kernel (determinism).
__device__ __forceinline__ float abar_of(const float* __restrict__ logA, int n) {
    float A = -expf(logA[n]);
    return expf(A * DT);
}

// ---- K1: local scan (zero init), store chunk-final states -----------------
__global__ __launch_bounds__(128, 7) void k_local(const float* __restrict__ x,
                                                  const float* __restrict__ logA) {
    __shared__ float xs[CPB][XPAD];
    const int p   = blockIdx.x;
    const int c0  = blockIdx.y * CPB;
    const int tid = threadIdx.x;

    // load x tile transposed: xs[cl][j] ; q fastest for gmem coalescing
    for (int i = tid; i < BCH * (CPB / 4); i += 128) {
        int q = i & 7, j = i >> 3;
        float4 v = *(const float4*)&x[(size_t)(p * BCH + j) * CH + c0 + q * 4];
        xs[q * 4 + 0][j] = v.x; xs[q * 4 + 1][j] = v.y;
        xs[q * 4 + 2][j] = v.z; xs[q * 4 + 3][j] = v.w;
    }

    const int g  = tid & 3;       // state group (16 states = 8 f32x2 pairs)
    const int cl = tid >> 2;      // channel within block (0..31)
    const int n0 = g * 16;

    ull a2[8], u2[8];
    #pragma unroll
    for (int k = 0; k < 8; k++) {
        a2[k] = f2pack(abar_of(logA, n0 + 2 * k), abar_of(logA, n0 + 2 * k + 1));
        u2[k] = 0ull;
    }
    __syncthreads();

    float4 xv = *(const float4*)&xs[cl][0];
    #pragma unroll 4
    for (int jb = 0; jb < BCH; jb += 4) {
        float4 cur = xv;
        int jn = (jb + 4 < BCH) ? jb + 4 : 0;
        xv = *(const float4*)&xs[cl][jn];        // prefetch next block
        float xq[4] = {cur.x, cur.y, cur.z, cur.w};
        #pragma unroll
        for (int s = 0; s < 4; s++) {
            ull xx = f2bcast(xq[s]);
            #pragma unroll
            for (int k = 0; k < 8; k++) u2[k] = f2fma(a2[k], u2[k], xx);
        }
    }

    ull* dst = (ull*)&g_Hl[((size_t)p * CH + (c0 + cl)) * NS + n0];
    #pragma unroll
    for (int k = 0; k < 8; k++) dst[k] = u2[k];
}

// ---- K2: carry scan across chunks (pairs of states) -----------------------
__global__ __launch_bounds__(128) void k_scan(const float* __restrict__ logA) {
    int idx = blockIdx.x * blockDim.x + threadIdx.x;   // pair index: c*32 + np
    if (idx >= CH * NS / 2) return;
    int np = idx & 31;
    // Abar^BCH via 7 double squarings (BCH = 128 = 2^7)
    double d0 = (double)abar_of(logA, 2 * np);
    double d1 = (double)abar_of(logA, 2 * np + 1);
    #pragma unroll
    for (int i = 0; i < 7; i++) { d0 *= d0; d1 *= d1; }
    ull aB2 = f2pack((float)d0, (float)d1);

    ull S = 0ull;
    const ull* Hl  = (const ull*)g_Hl;
    ull*       Hin = (ull*)g_Hin;
    const int stride = CH * NS / 2;
    #pragma unroll 8
    for (int p = 0; p < NP; p++) {
        Hin[(size_t)p * stride + idx] = S;
        S = f2fma(aB2, S, Hl[(size_t)p * stride + idx]);
    }
}

// ---- K3: seeded scan, emit y ----------------------------------------------
__global__ __launch_bounds__(128, 7) void k_final(const float* __restrict__ x,
                                                  const float* __restrict__ logA,
                                                  const float* __restrict__ Bp,
                                                  const float* __restrict__ Cp,
                                                  float* __restrict__ y) {
    __shared__ float xs[CPB][XPAD];
    const int p   = blockIdx.x;
    const int c0  = blockIdx.y * CPB;
    const int tid = threadIdx.x;

    for (int i = tid; i < BCH * (CPB / 4); i += 128) {
        int q = i & 7, j = i >> 3;
        float4 v = *(const float4*)&x[(size_t)(p * BCH + j) * CH + c0 + q * 4];
        xs[q * 4 + 0][j] = v.x; xs[q * 4 + 1][j] = v.y;
        xs[q * 4 + 2][j] = v.z; xs[q * 4 + 3][j] = v.w;
    }

    const int g  = tid & 3;
    const int cl = tid >> 2;
    const int n0 = g * 16;

    ull a2[8], w2[8], u2[8];
    {
        float af[16], wf[16];
        #pragma unroll
        for (int k = 0; k < 16; k++) {
            int n = n0 + k;
            float A    = -expf(logA[n]);
            float Abar = expf(A * DT);
            float Bbar = (Abar - 1.0f) * Bp[n] / A;
            af[k] = Abar;
            wf[k] = Cp[n] * Bbar;
        }
        #pragma unroll
        for (int k = 0; k < 8; k++) {
            a2[k] = f2pack(af[2 * k], af[2 * k + 1]);
            w2[k] = f2pack(wf[2 * k], wf[2 * k + 1]);
        }
    }
    const ull* hin = (const ull*)&g_Hin[((size_t)p * CH + (c0 + cl)) * NS + n0];
    #pragma unroll
    for (int k = 0; k < 8; k++) u2[k] = hin[k];
    __syncthreads();

    float4 xv = *(const float4*)&xs[cl][0];
    #pragma unroll 2
    for (int jb = 0; jb < BCH; jb += 4) {
        float4 cur = xv;
        int jn = (jb + 4 < BCH) ? jb + 4 : 0;
        xv = *(const float4*)&xs[cl][jn];        // prefetch next block
        float xq[4] = {cur.x, cur.y, cur.z, cur.w};
        float pt[4];
        #pragma unroll
        for (int s = 0; s < 4; s++) {
            ull xx = f2bcast(xq[s]);
            #pragma unroll
            for (int k = 0; k < 8; k++) u2[k] = f2fma(a2[k], u2[k], xx);
            ull s0 = f2mul(w2[0], u2[0]);
            ull s1 = f2mul(w2[1], u2[1]);
            #pragma unroll
            for (int k = 2; k < 8; k += 2) {
                s0 = f2fma(w2[k],     u2[k],     s0);
                s1 = f2fma(w2[k + 1], u2[k + 1], s1);
            }
            pt[s] = f2hsum(f2add(s0, s1));
        }
        // 4x4 sum-transpose across the quad: lane g ends with total for jb+g.
        float p0 = pt[0], p1 = pt[1], p2 = pt[2], p3 = pt[3];
        float send1 = (g & 1) ? p0 : p1;
        float r1 = __shfl_xor_sync(0xffffffffu, send1, 1);
        if (g & 1) p1 += r1; else p0 += r1;
        float send2 = (g & 1) ? p2 : p3;
        float r2 = __shfl_xor_sync(0xffffffffu, send2, 1);
        if (g & 1) p3 += r2; else p2 += r2;
        float send3 = (g & 2) ? ((g & 1) ? p1 : p0) : ((g & 1) ? p3 : p2);
        float r3 = __shfl_xor_sync(0xffffffffu, send3, 2);
        float total = ((g & 1) ? ((g & 2) ? p3 : p1) : ((g & 2) ? p2 : p0)) + r3;
        // in-place: y for timestep jb+g overwrites consumed x slot
        xs[cl][jb + g] = total;
    }
    __syncthreads();

    for (int i = tid; i < BCH * (CPB / 4); i += 128) {
        int q = i & 7, j = i >> 3;
        float4 v = make_float4(xs[q * 4 + 0][j], xs[q * 4 + 1][j],
                               xs[q * 4 + 2][j], xs[q * 4 + 3][j]);
        *(float4*)&y[(size_t)(p * BCH + j) * CH + c0 + q * 4] = v;
    }
}

extern "C" void kernel_launch(void* const* d_in, const int* in_sizes, int n_in,
                              void* d_out, int out_size) {
    const float* x    = (const float*)d_in[0];
    const float* logA = (const float*)d_in[1];
    const float* Bp   = (const float*)d_in[2];
    const float* Cp   = (const float*)d_in[3];
    float* y = (float*)d_out;

    dim3 grid(NP, CH / CPB);                 // 64 x 16 = 1024 blocks
    k_local<<<grid, 128>>>(x, logA);
    k_scan<<<(CH * NS / 2) / 128, 128>>>(logA);
    k_final<<<grid, 128>>>(x, logA, Bp, Cp, y);
}